// round 17
// baseline (speedup 1.0000x reference)
#include <cuda_runtime.h>
#include <math_constants.h>

// Problem constants (from reference setup_inputs)
#define BATCH   8
#define NPTS    4096
#define NSLOT   (2 * BATCH)          // 16 point clouds (x and y per batch)
#define TOTPTS  (NSLOT * NPTS)       // 65536

// Uniform grid over [-4.5, 4.5]^3, GD=20 (h=0.45). Outliers clamp to edge
// cells (bound-safe: clamped points are farther than their cell suggests).
#define GD      20
#define QROWS   (GD * GD)            // 400 (iz,iy) rows per slot
#define GSTRIDE 8192                 // padded per-slot cell stride (pads = 0)
#define NCELLS  (NSLOT * GSTRIDE)    // 131072
#define GRID_MIN  (-4.5f)
#define GRID_H    (9.0f / (float)GD)     // 0.45
#define GRID_INVH ((float)GD / 9.0f)

// Query: one warp per (slot,row); internal loop over 32-query chunks.
#define QTHR     128                 // 4 warps per block
#define NQWARPS  (NSLOT * QROWS)     // 6400
#define NQBLK    (NQWARPS / (QTHR / 32))  // 1600

#define PBLK    64
#define PTHR    256

// Scratch (no allocs). Replay invariant: g_counts is zero at kernel_launch
// entry (static zero-init; re-zeroed by partial_kernel each call). Everything
// else is fully overwritten before being read, every call.
__device__ int    g_counts[NCELLS];
__device__ int    g_starts[NCELLS];
__device__ int    g_cursor[NCELLS];       // post-scatter: cell end positions
__device__ float4 g_sorted[TOTPTS];       // (x, y, z, |p|^2/2)
__device__ int    g_qid[TOTPTS];          // original id per sorted position
__device__ float  g_res[TOTPTS];
__device__ float  g_partial[PBLK];

__device__ __forceinline__ int cell_of(float v) {
    int i = (int)floorf((v - GRID_MIN) * GRID_INVH);
    return min(max(i, 0), GD - 1);
}

__device__ __forceinline__ const float* point_ptr(const float* x, const float* y,
                                                  int gid) {
    int s = gid >> 12;
    int n = gid & (NPTS - 1);
    int b = s >> 1;
    const float* src = (s & 1) ? y : x;
    return src + ((size_t)b * NPTS + n) * 3;
}

// Fold candidates [t0,t1) into best: v = hq_c - p.q (seed form).
__device__ __forceinline__ void fold_range(const float4* __restrict__ tp,
                                           int t0, int t1,
                                           float nxp, float nyp, float nzp,
                                           float& best) {
#pragma unroll 4
    for (int t = t0; t < t1; t++) {
        float4 qq = tp[t];                       // warp-uniform broadcast
        float v = fmaf(nxp, qq.x, qq.w);
        v = fmaf(nyp, qq.y, v);
        v = fmaf(nzp, qq.z, v);
        best = fminf(best, v);
    }
}

// 1) Histogram points into cells.
__global__ __launch_bounds__(256)
void count_kernel(const float* __restrict__ x, const float* __restrict__ y) {
    int gid = blockIdx.x * 256 + threadIdx.x;
    const float* p = point_ptr(x, y, gid);
    int cell = (cell_of(p[2]) * GD + cell_of(p[1])) * GD + cell_of(p[0]);
    atomicAdd(&g_counts[(gid >> 12) * GSTRIDE + cell], 1);
}

// 2) Per-slot exclusive scan, one block per slot, fully coalesced int4.
__global__ __launch_bounds__(1024)
void scan_kernel() {
    __shared__ int wsum[32];
    __shared__ int wexcl[32];
    const int s = blockIdx.x;
    const int t = threadIdx.x;
    const int lane = t & 31;
    const int w = t >> 5;

    const int4* cp = (const int4*)(g_counts + s * GSTRIDE);
    int4 a = cp[2 * t];
    int4 b = cp[2 * t + 1];
    int tsum = a.x + a.y + a.z + a.w + b.x + b.y + b.z + b.w;

    int incl = tsum;
#pragma unroll
    for (int off = 1; off < 32; off <<= 1) {
        int u = __shfl_up_sync(0xFFFFFFFFu, incl, off);
        if (lane >= off) incl += u;
    }
    if (lane == 31) wsum[w] = incl;
    __syncthreads();
    if (w == 0) {
        int v = wsum[lane];
        int i2 = v;
#pragma unroll
        for (int off = 1; off < 32; off <<= 1) {
            int u = __shfl_up_sync(0xFFFFFFFFu, i2, off);
            if (lane >= off) i2 += u;
        }
        wexcl[lane] = i2 - v;
    }
    __syncthreads();

    int run = wexcl[w] + (incl - tsum);
    int4 s0, s1;
    s0.x = run;             run += a.x;
    s0.y = run;             run += a.y;
    s0.z = run;             run += a.z;
    s0.w = run;             run += a.w;
    s1.x = run;             run += b.x;
    s1.y = run;             run += b.y;
    s1.z = run;             run += b.z;
    s1.w = run;
    ((int4*)(g_starts + s * GSTRIDE))[2 * t]     = s0;
    ((int4*)(g_starts + s * GSTRIDE))[2 * t + 1] = s1;
    ((int4*)(g_cursor + s * GSTRIDE))[2 * t]     = s0;
    ((int4*)(g_cursor + s * GSTRIDE))[2 * t + 1] = s1;
}

// 3) Scatter points into cell-sorted order. .w = |p|^2/2; id goes to g_qid.
__global__ __launch_bounds__(256)
void scatter_kernel(const float* __restrict__ x, const float* __restrict__ y) {
    int gid = blockIdx.x * 256 + threadIdx.x;
    int s = gid >> 12;
    const float* p = point_ptr(x, y, gid);
    float px = p[0], py = p[1], pz = p[2];
    float hq = 0.5f * fmaf(pz, pz, fmaf(py, py, px * px));
    int cell = (cell_of(pz) * GD + cell_of(py)) * GD + cell_of(px);
    int pos = atomicAdd(&g_cursor[s * GSTRIDE + cell], 1);
    g_sorted[s * NPTS + pos] = make_float4(px, py, pz, hq);
    g_qid[s * NPTS + pos] = gid;
}

// 4) Exact NN, fully warp-cooperative. One warp per (slot, cell-row); loops
// over the row's queries in 32-chunks. Ring 1: 9 contiguous candidate
// row-ranges with warp-union x-window — every candidate load is a broadcast.
// r>=2 shells are ALSO warp-cooperative: ballot decides if any lane needs
// radius r; the shell is scanned with union windows (edge rows full range,
// interior rows two strips covering every lane's +/-r cells). Supersets are
// min-safe, so each lane's r*h termination bound stays exact.
__global__ __launch_bounds__(QTHR)
void query_kernel() {
    const int gw   = blockIdx.x * (QTHR / 32) + (threadIdx.x >> 5);
    const int lane = threadIdx.x & 31;
    const int qs  = gw / QROWS;
    const int row = gw - qs * QROWS;      // iz*GD + iy
    const int iz  = row / GD;
    const int iy  = row - iz * GD;
    const int ts  = qs ^ 1;

    const int rb = row * GD;
    const int rowstart = g_starts[qs * GSTRIDE + rb];
    const int rowend   = g_cursor[qs * GSTRIDE + rb + GD - 1];

    const int*    __restrict__ tst = g_starts + ts * GSTRIDE;
    const int*    __restrict__ ten = g_cursor + ts * GSTRIDE;
    const float4* __restrict__ tp  = g_sorted + ts * NPTS;

    for (int cstart = rowstart; cstart < rowend; cstart += 32) {
        const int nv = min(32, rowend - cstart);
        const bool valid = lane < nv;
        const int qidx = cstart + min(lane, nv - 1);

        const float4 pp = g_sorted[qs * NPTS + qidx];
        const float hp = pp.w;
        const float nxp = -pp.x, nyp = -pp.y, nzp = -pp.z;
        const int cx = cell_of(pp.x);
        const int cxmin = __shfl_sync(0xFFFFFFFFu, cx, 0);
        const int cxmax = __shfl_sync(0xFFFFFFFFu, cx, nv - 1);

        // best = min over candidates of (hq_c - p.q); d^2/2 = best + hp.
        float best = valid ? CUDART_INF_F : -CUDART_INF_F;

        // ---- Ring 0+1: 9 rows, union x-window, ranges batched. ----
        {
            const int x0 = max(cxmin - 1, 0), x1 = min(cxmax + 1, GD - 1);
            int c0[9], c1[9];
#pragma unroll
            for (int k = 0; k < 9; k++) {
                int z2 = iz + k / 3 - 1;
                int y2 = iy + k % 3 - 1;
                if (z2 >= 0 && z2 < GD && y2 >= 0 && y2 < GD) {
                    int rb2 = (z2 * GD + y2) * GD;
                    c0[k] = __ldg(&tst[rb2 + x0]);
                    c1[k] = __ldg(&ten[rb2 + x1]);
                } else {
                    c0[k] = 0;
                    c1[k] = 0;
                }
            }
#pragma unroll
            for (int k = 0; k < 9; k++)
                fold_range(tp, c0[k], c1[k], nxp, nyp, nzp, best);
        }

        // ---- Warp-cooperative expansion: shell at radius r if ANY lane
        //      still needs it (invalid lanes: best=-inf -> never need). ----
        float lim = GRID_H;
        unsigned need = __ballot_sync(0xFFFFFFFFu,
                                      2.0f * (best + hp) > lim * lim);
        for (int r = 2; need && r < GD; r++) {
            const int z0 = max(iz - r, 0), z1 = min(iz + r, GD - 1);
            const int yy0 = max(iy - r, 0), yy1 = min(iy + r, GD - 1);
            const int xf0 = max(cxmin - r, 0), xf1 = min(cxmax + r, GD - 1);
            for (int z2 = z0; z2 <= z1; z2++) {
                int az = abs(z2 - iz);
                for (int y2 = yy0; y2 <= yy1; y2++) {
                    int rb2 = (z2 * GD + y2) * GD;
                    if (az == r || abs(y2 - iy) == r) {
                        // edge row: full union window
                        fold_range(tp, __ldg(&tst[rb2 + xf0]),
                                   __ldg(&ten[rb2 + xf1]),
                                   nxp, nyp, nzp, best);
                    } else {
                        // interior row: the two +/-r strips (union over lanes)
                        if (cxmax - r >= 0) {
                            int l0 = max(cxmin - r, 0);
                            int l1 = min(cxmax - r, GD - 1);
                            fold_range(tp, __ldg(&tst[rb2 + l0]),
                                       __ldg(&ten[rb2 + l1]),
                                       nxp, nyp, nzp, best);
                        }
                        if (cxmin + r <= GD - 1) {
                            int u0 = max(cxmin + r, 0);
                            int u1 = min(cxmax + r, GD - 1);
                            fold_range(tp, __ldg(&tst[rb2 + u0]),
                                       __ldg(&ten[rb2 + u1]),
                                       nxp, nyp, nzp, best);
                        }
                    }
                }
            }
            lim = (float)r * GRID_H;
            need = __ballot_sync(0xFFFFFFFFu,
                                 2.0f * (best + hp) > lim * lim);
        }

        if (valid) {
            float d2 = fmaxf(2.0f * (best + hp), 0.0f);
            g_res[g_qid[qs * NPTS + qidx]] = sqrtf(d2);
        }
    }
}

// 5) Fixed-order partial sums over g_res; also resets g_counts for the next
//    graph replay (race-free: nothing reads counts after scan_kernel).
__global__ __launch_bounds__(PTHR)
void partial_kernel() {
    __shared__ float sh[PTHR];
    const int base = blockIdx.x * (TOTPTS / PBLK) + threadIdx.x;
    float v = 0.0f;
#pragma unroll
    for (int r = 0; r < TOTPTS / PBLK / PTHR; r++) v += g_res[base + r * PTHR];
    sh[threadIdx.x] = v;

    // counts reset: 32768 int4 over 16384 threads = 2 each
    {
        int4* zp = (int4*)g_counts;
        const int4 z4 = make_int4(0, 0, 0, 0);
        int i0 = blockIdx.x * PTHR + threadIdx.x;
        zp[i0] = z4;
        zp[i0 + PBLK * PTHR] = z4;
    }

    __syncthreads();
    for (int off = PTHR / 2; off > 0; off >>= 1) {
        if (threadIdx.x < off) sh[threadIdx.x] += sh[threadIdx.x + off];
        __syncthreads();
    }
    if (threadIdx.x == 0) g_partial[blockIdx.x] = sh[0];
}

// 6) Final fold.
__global__ __launch_bounds__(64)
void final_kernel(float* __restrict__ out) {
    __shared__ float sh[64];
    sh[threadIdx.x] = g_partial[threadIdx.x];
    __syncthreads();
    for (int off = 32; off > 0; off >>= 1) {
        if (threadIdx.x < off) sh[threadIdx.x] += sh[threadIdx.x + off];
        __syncthreads();
    }
    if (threadIdx.x == 0) out[0] = sh[0] / (float)(BATCH * NPTS);
}

extern "C" void kernel_launch(void* const* d_in, const int* in_sizes, int n_in,
                              void* d_out, int out_size) {
    const float* x = (const float*)d_in[0];
    const float* y = (const float*)d_in[1];
    float* out = (float*)d_out;

    count_kernel<<<TOTPTS / 256, 256>>>(x, y);
    scan_kernel<<<NSLOT, 1024>>>();
    scatter_kernel<<<TOTPTS / 256, 256>>>(x, y);
    query_kernel<<<NQBLK, QTHR>>>();
    partial_kernel<<<PBLK, PTHR>>>();
    final_kernel<<<1, 64>>>(out);
}